// round 2
// baseline (speedup 1.0000x reference)
#include <cuda_runtime.h>
#include <math.h>

// Shapes (fixed for this problem)
#define kB 4
#define kH 12
#define kS 2048
#define kD 64
#define BSv 64
#define Lv 32
#define NSTEPS 4
#define BH (kB*kH)

// ---------------- device scratch (module-load allocated) ----------------
__device__ float g_lp[(size_t)BH*BSv*Lv*Lv];      // [bh][j][l][k]
__device__ float g_rp[(size_t)BH*Lv*BSv*BSv];     // [bh][k][j][i]
__device__ float g_KR[(size_t)BH*Lv*BSv*kD];      // [bh][k][j][v]  (reused as Y at the end)
__device__ float g_LQ[(size_t)BH*BSv*Lv*kD];      // [bh][j][kk][v]
__device__ float g_r2[BH*Lv*BSv];                 // [bh][k][j]
__device__ float g_l2[BH*BSv*Lv];                 // [bh][j][k]
__device__ float g_Qs[(size_t)BH*kS*kD];          // scaled query
__device__ float g_leftF[(size_t)BH*BSv*Lv*Lv];   // final left [bh][j][l][k]
__device__ float g_eta[kH*2*NSTEPS];              // softplus(step_size)

__device__ __forceinline__ float softplusf(float x) {
    return x > 20.f ? x : log1pf(expf(x));
}

__device__ __forceinline__ float warp_allred(float v) {
    #pragma unroll
    for (int o = 16; o > 0; o >>= 1) v += __shfl_xor_sync(0xffffffffu, v, o);
    return v;
}

// ---------------- prep: Qs, lp/rp init, eta ----------------
__global__ void __launch_bounds__(256) prep_kernel(const float* __restrict__ query,
                                                   const float* __restrict__ ascale,
                                                   const float* __restrict__ ssize) {
    size_t i = (size_t)blockIdx.x * 256 + threadIdx.x;       // grid covers BH*S*D exactly
    __shared__ float s_sc;
    int h = (int)((i / ((size_t)kS * kD)) % kH);             // constant per block (S*D % 256 == 0)
    if (threadIdx.x == 0) s_sc = softplusf(ascale[h]) * rsqrtf((float)kD);
    __syncthreads();
    g_Qs[i] = query[i] * s_sc;

    size_t stride = (size_t)gridDim.x * 256;
    const size_t LPN = (size_t)BH*BSv*Lv*Lv;
    const size_t RPN = (size_t)BH*Lv*BSv*BSv;
    for (size_t t = i; t < LPN; t += stride) g_lp[t] = 0.17677669529663687f;   // 1/sqrt(32)
    for (size_t t = i; t < RPN; t += stride) g_rp[t] = 0.125f;                  // 1/sqrt(64)
    if (i < (size_t)kH*2*NSTEPS) g_eta[i] = softplusf(ssize[i]);
}

// ---------------- step-0 KR: right0 == 1/64 -> KR0 = colmean of K ----------------
__global__ void __launch_bounds__(256) init_kr_kernel(const float* __restrict__ key) {
    int bh = blockIdx.x / Lv;
    int k  = blockIdx.x % Lv;
    const float* Kt = key + ((size_t)bh*kS + (size_t)k*BSv) * kD;
    __shared__ float s_m[kD];
    int tid = threadIdx.x;
    if (tid < kD) {
        float s = 0.f;
        #pragma unroll 8
        for (int i = 0; i < BSv; i++) s += Kt[(size_t)i*kD + tid];
        s_m[tid] = s * (1.0f/64.0f);
    }
    __syncthreads();
    float* KRo = g_KR + ((size_t)(bh*Lv + k) * BSv) * kD;
    #pragma unroll
    for (int it = 0; it < (BSv*kD)/256; it++) {
        int idx = tid + it*256;
        KRo[idx] = s_m[idx & 63];
    }
    if (tid < BSv) g_r2[(bh*Lv + k)*BSv + tid] = 1.0f/64.0f;
}

// ---------------- left step: per (bh, j) ----------------
template<bool LAST>
__global__ void __launch_bounds__(256) left_step_kernel(int s) {
    __shared__ float s_lp[Lv][Lv];
    __shared__ float s_ls[Lv][Lv];
    __shared__ float s_left[Lv][Lv];
    __shared__ float s_dl[Lv][Lv];
    __shared__ float s_qT[kD][Lv + 2];     // [v][l], stride 34 (float2-aligned)
    __shared__ float s_krT[kD][Lv + 2];    // [v][k]
    __shared__ float s_invn[Lv];
    __shared__ float s_r2c[Lv];

    int bh = blockIdx.x / BSv;
    int j  = blockIdx.x % BSv;
    int h  = bh % kH;
    int tid  = threadIdx.x;
    int lane = tid & 31;
    int warp = tid >> 5;

    const size_t lp_base = ((size_t)(bh*BSv + j)) * (Lv*Lv);
    #pragma unroll
    for (int it = 0; it < 4; it++) {
        int idx = tid + it*256;
        ((float*)s_lp)[idx] = g_lp[lp_base + idx];
    }
    if (tid < Lv) s_r2c[tid] = g_r2[(bh*Lv + tid)*BSv + j];
    __syncthreads();

    // row-normalize lp over k (warp w owns rows w, w+8, w+16, w+24)
    #pragma unroll
    for (int r = 0; r < 4; r++) {
        int l = warp + r*8;
        float x  = s_lp[l][lane];
        float ss = warp_allred(x*x);
        float n  = sqrtf(ss);
        float sc = n > 0.f ? 1.0f/n : 1.0f;
        float ls = x * sc;
        s_ls[l][lane]   = ls;
        s_left[l][lane] = ls*ls;
        if (lane == 0) s_invn[l] = n > 0.f ? 1.0f/n : 0.f;
    }
    __syncthreads();

    // l2[k] = sum_l left^2
    if (tid < Lv) {
        float acc = 0.f;
        #pragma unroll
        for (int l = 0; l < Lv; l++) { float v = s_left[l][tid]; acc += v*v; }
        g_l2[(size_t)(bh*BSv + j)*Lv + tid] = acc;
    }

    // load Q_j and KR_j, transposed into smem
    const float* Qb  = g_Qs + (size_t)bh*kS*kD;
    const float* KRb = g_KR + (size_t)bh*Lv*BSv*kD;
    #pragma unroll
    for (int it = 0; it < 8; it++) {
        int idx = tid + it*256;
        int row = idx >> 6;
        int v   = idx & 63;
        s_qT[v][row]  = Qb [((size_t)(row*BSv + j))*kD + v];
        s_krT[v][row] = KRb[((size_t)(row*BSv + j))*kD + v];
    }
    __syncthreads();

    // t2l[l][k] = sum_v q[l][v]*kr[k][v]   (16x16 threads, 2x2 tiles)
    {
        int tx = tid & 15, ty = tid >> 4;
        int l0 = ty*2, k0 = tx*2;
        float a00=0.f,a01=0.f,a10=0.f,a11=0.f;
        #pragma unroll
        for (int v = 0; v < kD; v++) {
            float2 a = *(const float2*)&s_qT[v][l0];
            float2 b = *(const float2*)&s_krT[v][k0];
            a00 += a.x*b.x; a01 += a.x*b.y;
            a10 += a.y*b.x; a11 += a.y*b.y;
        }
        s_dl[l0][k0]   = a00; s_dl[l0][k0+1]   = a01;
        s_dl[l0+1][k0] = a10; s_dl[l0+1][k0+1] = a11;
    }
    __syncthreads();

    // dl = (r2*left - t2l)*2*ls ; project ; * inv_norm
    #pragma unroll
    for (int r = 0; r < 4; r++) {
        int l = warp + r*8;
        float ls = s_ls[l][lane];
        float dl = s_r2c[lane]*s_left[l][lane] - s_dl[l][lane];
        dl *= 2.f*ls;
        float dot = warp_allred(ls*dl);
        dl = (dl - ls*dot) * s_invn[l];
        s_dl[l][lane] = dl;
    }
    __syncthreads();

    // LQ[kk][v] = sum_l left[l][kk]*q[l][v]   (pre-update left)
    float* LQo = g_LQ + ((size_t)(bh*BSv + j)) * Lv * kD;
    #pragma unroll
    for (int it = 0; it < 8; it++) {
        int idx = tid + it*256;
        int kk = idx >> 6;
        int v  = idx & 63;
        float acc = 0.f;
        #pragma unroll
        for (int l = 0; l < Lv; l++)
            acc += s_left[l][kk] * s_qT[v][l];
        LQo[idx] = acc;
    }

    // update lp
    float eta = g_eta[h*(2*NSTEPS) + s];
    #pragma unroll
    for (int it = 0; it < 4; it++) {
        int idx = tid + it*256;
        float nv = ((float*)s_lp)[idx] - eta * ((float*)s_dl)[idx];
        g_lp[lp_base + idx] = nv;
        if (LAST) ((float*)s_lp)[idx] = nv;
    }
    if (LAST) {
        __syncthreads();
        #pragma unroll
        for (int r = 0; r < 4; r++) {
            int l = warp + r*8;
            float x  = s_lp[l][lane];
            float ss = warp_allred(x*x);
            float n  = sqrtf(ss);
            float sc = n > 0.f ? 1.0f/n : 1.0f;
            float v  = x*sc;
            g_leftF[lp_base + l*Lv + lane] = v*v;
        }
    }
}

// ---------------- right step: per (bh, k) ----------------
#define C_PAD 68
#define SMEM_C_FLOATS (4096*3 + 4352*2 + 192)

template<int MODE>  // 0 = update rp + compute next KR/r2 ; 1 = last step: compute Y from V
__global__ void __launch_bounds__(256) right_step_kernel(const float* __restrict__ key,
                                                         const float* __restrict__ val,
                                                         int s) {
    extern __shared__ float sm[];
    float* s_rs   = sm;                  // 64x64: rp -> rs -> rs_new
    float* s_Km   = s_rs  + 4096;        // 64x64 row-major K (or V)
    float* s_KT   = s_Km  + 4096;        // [v][i], stride 68
    float* s_LQT  = s_KT  + 4352;        // [v][j], stride 68 ; later rightT[i][j]
    float* s_t2r  = s_LQT + 4352;        // 64x64
    float* s_n    = s_t2r + 4096;        // 64
    float* s_invn = s_n    + 64;
    float* s_l2   = s_invn + 64;

    int bh = blockIdx.x / Lv;
    int k  = blockIdx.x % Lv;
    int h  = bh % kH;
    int tid  = threadIdx.x;
    int lane = tid & 31;
    int warp = tid >> 5;

    const size_t rp_base = ((size_t)(bh*Lv + k)) * (BSv*BSv);
    const float* Kt  = key + ((size_t)bh*kS + (size_t)k*BSv) * kD;
    const float* LQb = g_LQ + (size_t)bh*BSv*Lv*kD + (size_t)k*kD;

    #pragma unroll
    for (int it = 0; it < 16; it++) {
        int idx = tid + it*256;
        s_rs[idx] = g_rp[rp_base + idx];
        int row = idx >> 6, v = idx & 63;
        float kv = Kt[idx];
        s_KT[v*C_PAD + row] = kv;
        if (MODE == 0) s_Km[idx] = kv;
        s_LQT[v*C_PAD + row] = LQb[(size_t)row*(Lv*kD) + v];
    }
    if (tid < BSv) s_l2[tid] = g_l2[(size_t)(bh*BSv + tid)*Lv + k];
    __syncthreads();

    // normalize rp rows over i (warp w owns rows w, w+8, ..., lanes cover i=lane,lane+32)
    #pragma unroll
    for (int r = 0; r < 8; r++) {
        int j = warp + r*8;
        float x0 = s_rs[j*BSv + lane];
        float x1 = s_rs[j*BSv + lane + 32];
        float ss = warp_allred(x0*x0 + x1*x1);
        float n  = sqrtf(ss);
        float sc = n > 0.f ? 1.0f/n : 1.0f;
        s_rs[j*BSv + lane]      = x0*sc;
        s_rs[j*BSv + lane + 32] = x1*sc;
        if (lane == 0) { s_n[j] = n > 0.f ? n : 1.0f; s_invn[j] = n > 0.f ? 1.0f/n : 0.f; }
    }
    __syncthreads();

    // t2r[j][i] = sum_v LQ[j][v]*K[i][v]   (16x16 threads, 4x4 tiles)
    {
        int tx = tid & 15, ty = tid >> 4;
        int j0 = ty*4, i0 = tx*4;
        float acc[4][4] = {};
        #pragma unroll
        for (int v = 0; v < kD; v++) {
            float4 a4 = *(const float4*)&s_LQT[v*C_PAD + j0];
            float4 b4 = *(const float4*)&s_KT[v*C_PAD + i0];
            float a[4] = {a4.x,a4.y,a4.z,a4.w};
            float b[4] = {b4.x,b4.y,b4.z,b4.w};
            #pragma unroll
            for (int r = 0; r < 4; r++)
                #pragma unroll
                for (int c = 0; c < 4; c++)
                    acc[r][c] += a[r]*b[c];
        }
        #pragma unroll
        for (int r = 0; r < 4; r++)
            *(float4*)&s_t2r[(j0+r)*BSv + i0] =
                make_float4(acc[r][0],acc[r][1],acc[r][2],acc[r][3]);
    }
    __syncthreads();

    // dr, project, update rp, renormalize -> rs_new (in place)
    float eta = g_eta[h*(2*NSTEPS) + NSTEPS + s];
    #pragma unroll
    for (int r = 0; r < 8; r++) {
        int j = warp + r*8;
        float rs0 = s_rs[j*BSv + lane], rs1 = s_rs[j*BSv + lane + 32];
        float l2v = s_l2[j];
        float t0 = s_t2r[j*BSv + lane], t1 = s_t2r[j*BSv + lane + 32];
        float dr0 = (l2v*rs0*rs0 - t0) * 2.f * rs0;
        float dr1 = (l2v*rs1*rs1 - t1) * 2.f * rs1;
        float dot = warp_allred(rs0*dr0 + rs1*dr1);
        float invn = s_invn[j];
        dr0 = (dr0 - rs0*dot) * invn;
        dr1 = (dr1 - rs1*dot) * invn;
        float nf = s_n[j];
        float rp0 = rs0*nf - eta*dr0;
        float rp1 = rs1*nf - eta*dr1;
        if (MODE == 0) {
            g_rp[rp_base + j*BSv + lane]      = rp0;
            g_rp[rp_base + j*BSv + lane + 32] = rp1;
        }
        float ss2 = warp_allred(rp0*rp0 + rp1*rp1);
        float n2  = sqrtf(ss2);
        float sc2 = n2 > 0.f ? 1.0f/n2 : 1.0f;
        float rsn0 = rp0*sc2, rsn1 = rp1*sc2;
        s_rs[j*BSv + lane]      = rsn0;
        s_rs[j*BSv + lane + 32] = rsn1;
        if (MODE == 0) {
            float rt0 = rsn0*rsn0, rt1 = rsn1*rsn1;
            float r2s = warp_allred(rt0*rt0 + rt1*rt1);
            if (lane == 0) g_r2[(bh*Lv + k)*BSv + j] = r2s;
        }
    }
    __syncthreads();

    // rightT[i][j] = rs_new[j][i]^2 (overwrite s_LQT) ; MODE1: load V into s_Km
    #pragma unroll
    for (int it = 0; it < 16; it++) {
        int idx = tid + it*256;
        int j2 = idx >> 6, i2 = idx & 63;
        float rv = s_rs[idx];
        s_LQT[i2*C_PAD + j2] = rv*rv;
    }
    if (MODE == 1) {
        const float* Vt = val + ((size_t)bh*kS + (size_t)k*BSv) * kD;
        #pragma unroll
        for (int it = 0; it < 16; it++) {
            int idx = tid + it*256;
            s_Km[idx] = Vt[idx];
        }
    }
    __syncthreads();

    // OUT[j][v] = sum_i rightT[i][j] * Km[i][v]  -> g_KR (next KR, or Y at last step)
    float* outp = g_KR + ((size_t)(bh*Lv + k) * BSv) * kD;
    {
        int tx = tid & 15, ty = tid >> 4;
        int j0 = ty*4, v0 = tx*4;
        float acc[4][4] = {};
        #pragma unroll
        for (int i = 0; i < BSv; i++) {
            float4 a4 = *(const float4*)&s_LQT[i*C_PAD + j0];
            float4 b4 = *(const float4*)&s_Km[i*kD + v0];
            float a[4] = {a4.x,a4.y,a4.z,a4.w};
            float b[4] = {b4.x,b4.y,b4.z,b4.w};
            #pragma unroll
            for (int r = 0; r < 4; r++)
                #pragma unroll
                for (int c = 0; c < 4; c++)
                    acc[r][c] += a[r]*b[c];
        }
        #pragma unroll
        for (int r = 0; r < 4; r++)
            *(float4*)&outp[(size_t)(j0+r)*kD + v0] =
                make_float4(acc[r][0],acc[r][1],acc[r][2],acc[r][3]);
    }
}

// ---------------- final Z = left @ Y, scatter to output ----------------
__global__ void __launch_bounds__(256) zout_kernel(float* __restrict__ out) {
    __shared__ float s_left[Lv][Lv];
    __shared__ float s_y[Lv][kD];
    int bh = blockIdx.x / BSv;
    int j  = blockIdx.x % BSv;
    int tid = threadIdx.x;
    size_t lbase = ((size_t)(bh*BSv + j)) * (Lv*Lv);
    #pragma unroll
    for (int it = 0; it < 4; it++) {
        int idx = tid + it*256;
        ((float*)s_left)[idx] = g_leftF[lbase + idx];
    }
    const float* Yb = g_KR + (size_t)bh*Lv*BSv*kD + (size_t)j*kD;
    #pragma unroll
    for (int it = 0; it < 8; it++) {
        int idx = tid + it*256;
        int kk = idx >> 6, v = idx & 63;
        s_y[kk][v] = Yb[(size_t)kk*(BSv*kD) + v];
    }
    __syncthreads();
    #pragma unroll
    for (int it = 0; it < 8; it++) {
        int idx = tid + it*256;
        int l = idx >> 6, v = idx & 63;
        float acc = 0.f;
        #pragma unroll
        for (int kk = 0; kk < Lv; kk++)
            acc += s_left[l][kk] * s_y[kk][v];
        out[((size_t)bh*kS + (size_t)l*BSv + j)*kD + v] = acc;
    }
}

// ---------------- launch ----------------
extern "C" void kernel_launch(void* const* d_in, const int* in_sizes, int n_in,
                              void* d_out, int out_size) {
    (void)in_sizes; (void)n_in; (void)out_size;
    const float* q      = (const float*)d_in[0];
    const float* key    = (const float*)d_in[1];
    const float* val    = (const float*)d_in[2];
    const float* ascale = (const float*)d_in[3];
    const float* ssz    = (const float*)d_in[4];
    float* out = (float*)d_out;

    const size_t SMEM_C = (size_t)SMEM_C_FLOATS * sizeof(float);
    cudaFuncSetAttribute(right_step_kernel<0>, cudaFuncAttributeMaxDynamicSharedMemorySize, (int)SMEM_C);
    cudaFuncSetAttribute(right_step_kernel<1>, cudaFuncAttributeMaxDynamicSharedMemorySize, (int)SMEM_C);

    int nq_blocks = (BH*kS*kD) / 256;
    prep_kernel<<<nq_blocks, 256>>>(q, ascale, ssz);
    init_kr_kernel<<<BH*Lv, 256>>>(key);
    for (int s = 0; s < NSTEPS; s++) {
        if (s < NSTEPS-1) {
            left_step_kernel<false><<<BH*BSv, 256>>>(s);
            right_step_kernel<0><<<BH*Lv, 256, SMEM_C>>>(key, val, s);
        } else {
            left_step_kernel<true><<<BH*BSv, 256>>>(s);
            right_step_kernel<1><<<BH*Lv, 256, SMEM_C>>>(key, val, s);
        }
    }
    zout_kernel<<<BH*BSv, 256>>>(out);
}

// round 3
// speedup vs baseline: 1.0007x; 1.0007x over previous
#include <cuda_runtime.h>
#include <math.h>

// Shapes (fixed for this problem)
#define kB 4
#define kH 12
#define kS 2048
#define kD 64
#define BSv 64
#define Lv 32
#define NSTEPS 4
#define BH (kB*kH)

// ---------------- device scratch (module-load allocated) ----------------
__device__ float g_lp[(size_t)BH*BSv*Lv*Lv];      // [bh][j][l][k]
__device__ float g_rp[(size_t)BH*Lv*BSv*BSv];     // [bh][k][j][i]
__device__ float g_KR[(size_t)BH*Lv*BSv*kD];      // [bh][k][j][v]  (reused as Y at the end)
__device__ float g_LQ[(size_t)BH*BSv*Lv*kD];      // [bh][j][kk][v]
__device__ float g_r2[BH*Lv*BSv];                 // [bh][k][j]
__device__ float g_l2[BH*BSv*Lv];                 // [bh][j][k]
__device__ float g_Qs[(size_t)BH*kS*kD];          // scaled query
__device__ float g_leftF[(size_t)BH*BSv*Lv*Lv];   // final left [bh][j][l][k]
__device__ float g_eta[kH*2*NSTEPS];              // softplus(step_size)

__device__ __forceinline__ float softplusf(float x) {
    return x > 20.f ? x : log1pf(expf(x));
}

__device__ __forceinline__ float warp_allred(float v) {
    #pragma unroll
    for (int o = 16; o > 0; o >>= 1) v += __shfl_xor_sync(0xffffffffu, v, o);
    return v;
}

// ---------------- prep: Qs, lp/rp init, eta ----------------
__global__ void __launch_bounds__(256) prep_kernel(const float* __restrict__ query,
                                                   const float* __restrict__ ascale,
                                                   const float* __restrict__ ssize) {
    size_t i = (size_t)blockIdx.x * 256 + threadIdx.x;       // grid covers BH*S*D exactly
    __shared__ float s_sc;
    int h = (int)((i / ((size_t)kS * kD)) % kH);             // constant per block (S*D % 256 == 0)
    if (threadIdx.x == 0) s_sc = softplusf(ascale[h]) * rsqrtf((float)kD);
    __syncthreads();
    g_Qs[i] = query[i] * s_sc;

    size_t stride = (size_t)gridDim.x * 256;
    const size_t LPN = (size_t)BH*BSv*Lv*Lv;
    const size_t RPN = (size_t)BH*Lv*BSv*BSv;
    for (size_t t = i; t < LPN; t += stride) g_lp[t] = 0.17677669529663687f;   // 1/sqrt(32)
    for (size_t t = i; t < RPN; t += stride) g_rp[t] = 0.125f;                  // 1/sqrt(64)
    if (i < (size_t)kH*2*NSTEPS) g_eta[i] = softplusf(ssize[i]);
}

// ---------------- step-0 KR: right0 == 1/64 -> KR0 = colmean of K ----------------
__global__ void __launch_bounds__(256) init_kr_kernel(const float* __restrict__ key) {
    int bh = blockIdx.x / Lv;
    int k  = blockIdx.x % Lv;
    const float* Kt = key + ((size_t)bh*kS + (size_t)k*BSv) * kD;
    __shared__ float s_m[kD];
    int tid = threadIdx.x;
    if (tid < kD) {
        float s = 0.f;
        #pragma unroll 8
        for (int i = 0; i < BSv; i++) s += Kt[(size_t)i*kD + tid];
        s_m[tid] = s * (1.0f/64.0f);
    }
    __syncthreads();
    float* KRo = g_KR + ((size_t)(bh*Lv + k) * BSv) * kD;
    #pragma unroll
    for (int it = 0; it < (BSv*kD)/256; it++) {
        int idx = tid + it*256;
        KRo[idx] = s_m[idx & 63];
    }
    if (tid < BSv) g_r2[(bh*Lv + k)*BSv + tid] = 1.0f/64.0f;
}

// ---------------- left step: per (bh, j) ----------------
template<bool LAST>
__global__ void __launch_bounds__(256) left_step_kernel(int s) {
    __shared__ float s_lp[Lv][Lv];
    __shared__ float s_ls[Lv][Lv];
    __shared__ float s_left[Lv][Lv];
    __shared__ float s_dl[Lv][Lv];
    __shared__ float s_qT[kD][Lv + 2];     // [v][l], stride 34 (float2-aligned)
    __shared__ float s_krT[kD][Lv + 2];    // [v][k]
    __shared__ float s_invn[Lv];
    __shared__ float s_r2c[Lv];

    int bh = blockIdx.x / BSv;
    int j  = blockIdx.x % BSv;
    int h  = bh % kH;
    int tid  = threadIdx.x;
    int lane = tid & 31;
    int warp = tid >> 5;

    const size_t lp_base = ((size_t)(bh*BSv + j)) * (Lv*Lv);
    #pragma unroll
    for (int it = 0; it < 4; it++) {
        int idx = tid + it*256;
        ((float*)s_lp)[idx] = g_lp[lp_base + idx];
    }
    if (tid < Lv) s_r2c[tid] = g_r2[(bh*Lv + tid)*BSv + j];
    __syncthreads();

    // row-normalize lp over k (warp w owns rows w, w+8, w+16, w+24)
    #pragma unroll
    for (int r = 0; r < 4; r++) {
        int l = warp + r*8;
        float x  = s_lp[l][lane];
        float ss = warp_allred(x*x);
        float n  = sqrtf(ss);
        float sc = n > 0.f ? 1.0f/n : 1.0f;
        float ls = x * sc;
        s_ls[l][lane]   = ls;
        s_left[l][lane] = ls*ls;
        if (lane == 0) s_invn[l] = n > 0.f ? 1.0f/n : 0.f;
    }
    __syncthreads();

    // l2[k] = sum_l left^2
    if (tid < Lv) {
        float acc = 0.f;
        #pragma unroll
        for (int l = 0; l < Lv; l++) { float v = s_left[l][tid]; acc += v*v; }
        g_l2[(size_t)(bh*BSv + j)*Lv + tid] = acc;
    }

    // load Q_j and KR_j, transposed into smem
    const float* Qb  = g_Qs + (size_t)bh*kS*kD;
    const float* KRb = g_KR + (size_t)bh*Lv*BSv*kD;
    #pragma unroll
    for (int it = 0; it < 8; it++) {
        int idx = tid + it*256;
        int row = idx >> 6;
        int v   = idx & 63;
        s_qT[v][row]  = Qb [((size_t)(row*BSv + j))*kD + v];
        s_krT[v][row] = KRb[((size_t)(row*BSv + j))*kD + v];
    }
    __syncthreads();

    // t2l[l][k] = sum_v q[l][v]*kr[k][v]   (16x16 threads, 2x2 tiles)
    {
        int tx = tid & 15, ty = tid >> 4;
        int l0 = ty*2, k0 = tx*2;
        float a00=0.f,a01=0.f,a10=0.f,a11=0.f;
        #pragma unroll
        for (int v = 0; v < kD; v++) {
            float2 a = *(const float2*)&s_qT[v][l0];
            float2 b = *(const float2*)&s_krT[v][k0];
            a00 += a.x*b.x; a01 += a.x*b.y;
            a10 += a.y*b.x; a11 += a.y*b.y;
        }
        s_dl[l0][k0]   = a00; s_dl[l0][k0+1]   = a01;
        s_dl[l0+1][k0] = a10; s_dl[l0+1][k0+1] = a11;
    }
    __syncthreads();

    // dl = (r2*left - t2l)*2*ls ; project ; * inv_norm
    #pragma unroll
    for (int r = 0; r < 4; r++) {
        int l = warp + r*8;
        float ls = s_ls[l][lane];
        float dl = s_r2c[lane]*s_left[l][lane] - s_dl[l][lane];
        dl *= 2.f*ls;
        float dot = warp_allred(ls*dl);
        dl = (dl - ls*dot) * s_invn[l];
        s_dl[l][lane] = dl;
    }
    __syncthreads();

    // LQ[kk][v] = sum_l left[l][kk]*q[l][v]   (pre-update left)
    float* LQo = g_LQ + ((size_t)(bh*BSv + j)) * Lv * kD;
    #pragma unroll
    for (int it = 0; it < 8; it++) {
        int idx = tid + it*256;
        int kk = idx >> 6;
        int v  = idx & 63;
        float acc = 0.f;
        #pragma unroll
        for (int l = 0; l < Lv; l++)
            acc += s_left[l][kk] * s_qT[v][l];
        LQo[idx] = acc;
    }

    // update lp
    float eta = g_eta[h*(2*NSTEPS) + s];
    #pragma unroll
    for (int it = 0; it < 4; it++) {
        int idx = tid + it*256;
        float nv = ((float*)s_lp)[idx] - eta * ((float*)s_dl)[idx];
        g_lp[lp_base + idx] = nv;
        if (LAST) ((float*)s_lp)[idx] = nv;
    }
    if (LAST) {
        __syncthreads();
        #pragma unroll
        for (int r = 0; r < 4; r++) {
            int l = warp + r*8;
            float x  = s_lp[l][lane];
            float ss = warp_allred(x*x);
            float n  = sqrtf(ss);
            float sc = n > 0.f ? 1.0f/n : 1.0f;
            float v  = x*sc;
            g_leftF[lp_base + l*Lv + lane] = v*v;
        }
    }
}

// ---------------- right step: per (bh, k) ----------------
#define C_PAD 68
#define SMEM_C_FLOATS (4096*3 + 4352*2 + 192)

template<int MODE>  // 0 = update rp + compute next KR/r2 ; 1 = last step: compute Y from V
__global__ void __launch_bounds__(256) right_step_kernel(const float* __restrict__ key,
                                                         const float* __restrict__ val,
                                                         int s) {
    extern __shared__ float sm[];
    float* s_rs   = sm;                  // 64x64: rp -> rs -> rs_new
    float* s_Km   = s_rs  + 4096;        // 64x64 row-major K (or V)
    float* s_KT   = s_Km  + 4096;        // [v][i], stride 68
    float* s_LQT  = s_KT  + 4352;        // [v][j], stride 68 ; later rightT[i][j]
    float* s_t2r  = s_LQT + 4352;        // 64x64
    float* s_n    = s_t2r + 4096;        // 64
    float* s_invn = s_n    + 64;
    float* s_l2   = s_invn + 64;

    int bh = blockIdx.x / Lv;
    int k  = blockIdx.x % Lv;
    int h  = bh % kH;
    int tid  = threadIdx.x;
    int lane = tid & 31;
    int warp = tid >> 5;

    const size_t rp_base = ((size_t)(bh*Lv + k)) * (BSv*BSv);
    const float* Kt  = key + ((size_t)bh*kS + (size_t)k*BSv) * kD;
    const float* LQb = g_LQ + (size_t)bh*BSv*Lv*kD + (size_t)k*kD;

    #pragma unroll
    for (int it = 0; it < 16; it++) {
        int idx = tid + it*256;
        s_rs[idx] = g_rp[rp_base + idx];
        int row = idx >> 6, v = idx & 63;
        float kv = Kt[idx];
        s_KT[v*C_PAD + row] = kv;
        if (MODE == 0) s_Km[idx] = kv;
        s_LQT[v*C_PAD + row] = LQb[(size_t)row*(Lv*kD) + v];
    }
    if (tid < BSv) s_l2[tid] = g_l2[(size_t)(bh*BSv + tid)*Lv + k];
    __syncthreads();

    // normalize rp rows over i (warp w owns rows w, w+8, ..., lanes cover i=lane,lane+32)
    #pragma unroll
    for (int r = 0; r < 8; r++) {
        int j = warp + r*8;
        float x0 = s_rs[j*BSv + lane];
        float x1 = s_rs[j*BSv + lane + 32];
        float ss = warp_allred(x0*x0 + x1*x1);
        float n  = sqrtf(ss);
        float sc = n > 0.f ? 1.0f/n : 1.0f;
        s_rs[j*BSv + lane]      = x0*sc;
        s_rs[j*BSv + lane + 32] = x1*sc;
        if (lane == 0) { s_n[j] = n > 0.f ? n : 1.0f; s_invn[j] = n > 0.f ? 1.0f/n : 0.f; }
    }
    __syncthreads();

    // t2r[j][i] = sum_v LQ[j][v]*K[i][v]   (16x16 threads, 4x4 tiles)
    {
        int tx = tid & 15, ty = tid >> 4;
        int j0 = ty*4, i0 = tx*4;
        float acc[4][4] = {};
        #pragma unroll
        for (int v = 0; v < kD; v++) {
            float4 a4 = *(const float4*)&s_LQT[v*C_PAD + j0];
            float4 b4 = *(const float4*)&s_KT[v*C_PAD + i0];
            float a[4] = {a4.x,a4.y,a4.z,a4.w};
            float b[4] = {b4.x,b4.y,b4.z,b4.w};
            #pragma unroll
            for (int r = 0; r < 4; r++)
                #pragma unroll
                for (int c = 0; c < 4; c++)
                    acc[r][c] += a[r]*b[c];
        }
        #pragma unroll
        for (int r = 0; r < 4; r++)
            *(float4*)&s_t2r[(j0+r)*BSv + i0] =
                make_float4(acc[r][0],acc[r][1],acc[r][2],acc[r][3]);
    }
    __syncthreads();

    // dr, project, update rp, renormalize -> rs_new (in place)
    float eta = g_eta[h*(2*NSTEPS) + NSTEPS + s];
    #pragma unroll
    for (int r = 0; r < 8; r++) {
        int j = warp + r*8;
        float rs0 = s_rs[j*BSv + lane], rs1 = s_rs[j*BSv + lane + 32];
        float l2v = s_l2[j];
        float t0 = s_t2r[j*BSv + lane], t1 = s_t2r[j*BSv + lane + 32];
        float dr0 = (l2v*rs0*rs0 - t0) * 2.f * rs0;
        float dr1 = (l2v*rs1*rs1 - t1) * 2.f * rs1;
        float dot = warp_allred(rs0*dr0 + rs1*dr1);
        float invn = s_invn[j];
        dr0 = (dr0 - rs0*dot) * invn;
        dr1 = (dr1 - rs1*dot) * invn;
        float nf = s_n[j];
        float rp0 = rs0*nf - eta*dr0;
        float rp1 = rs1*nf - eta*dr1;
        if (MODE == 0) {
            g_rp[rp_base + j*BSv + lane]      = rp0;
            g_rp[rp_base + j*BSv + lane + 32] = rp1;
        }
        float ss2 = warp_allred(rp0*rp0 + rp1*rp1);
        float n2  = sqrtf(ss2);
        float sc2 = n2 > 0.f ? 1.0f/n2 : 1.0f;
        float rsn0 = rp0*sc2, rsn1 = rp1*sc2;
        s_rs[j*BSv + lane]      = rsn0;
        s_rs[j*BSv + lane + 32] = rsn1;
        if (MODE == 0) {
            float rt0 = rsn0*rsn0, rt1 = rsn1*rsn1;
            float r2s = warp_allred(rt0*rt0 + rt1*rt1);
            if (lane == 0) g_r2[(bh*Lv + k)*BSv + j] = r2s;
        }
    }
    __syncthreads();

    // rightT[i][j] = rs_new[j][i]^2 (overwrite s_LQT) ; MODE1: load V into s_Km
    #pragma unroll
    for (int it = 0; it < 16; it++) {
        int idx = tid + it*256;
        int j2 = idx >> 6, i2 = idx & 63;
        float rv = s_rs[idx];
        s_LQT[i2*C_PAD + j2] = rv*rv;
    }
    if (MODE == 1) {
        const float* Vt = val + ((size_t)bh*kS + (size_t)k*BSv) * kD;
        #pragma unroll
        for (int it = 0; it < 16; it++) {
            int idx = tid + it*256;
            s_Km[idx] = Vt[idx];
        }
    }
    __syncthreads();

    // OUT[j][v] = sum_i rightT[i][j] * Km[i][v]  -> g_KR (next KR, or Y at last step)
    float* outp = g_KR + ((size_t)(bh*Lv + k) * BSv) * kD;
    {
        int tx = tid & 15, ty = tid >> 4;
        int j0 = ty*4, v0 = tx*4;
        float acc[4][4] = {};
        #pragma unroll
        for (int i = 0; i < BSv; i++) {
            float4 a4 = *(const float4*)&s_LQT[i*C_PAD + j0];
            float4 b4 = *(const float4*)&s_Km[i*kD + v0];
            float a[4] = {a4.x,a4.y,a4.z,a4.w};
            float b[4] = {b4.x,b4.y,b4.z,b4.w};
            #pragma unroll
            for (int r = 0; r < 4; r++)
                #pragma unroll
                for (int c = 0; c < 4; c++)
                    acc[r][c] += a[r]*b[c];
        }
        #pragma unroll
        for (int r = 0; r < 4; r++)
            *(float4*)&outp[(size_t)(j0+r)*kD + v0] =
                make_float4(acc[r][0],acc[r][1],acc[r][2],acc[r][3]);
    }
}

// ---------------- final Z = left @ Y, scatter to output ----------------
__global__ void __launch_bounds__(256) zout_kernel(float* __restrict__ out) {
    __shared__ float s_left[Lv][Lv];
    __shared__ float s_y[Lv][kD];
    int bh = blockIdx.x / BSv;
    int j  = blockIdx.x % BSv;
    int tid = threadIdx.x;
    size_t lbase = ((size_t)(bh*BSv + j)) * (Lv*Lv);
    #pragma unroll
    for (int it = 0; it < 4; it++) {
        int idx = tid + it*256;
        ((float*)s_left)[idx] = g_leftF[lbase + idx];
    }
    const float* Yb = g_KR + (size_t)bh*Lv*BSv*kD + (size_t)j*kD;
    #pragma unroll
    for (int it = 0; it < 8; it++) {
        int idx = tid + it*256;
        int kk = idx >> 6, v = idx & 63;
        s_y[kk][v] = Yb[(size_t)kk*(BSv*kD) + v];
    }
    __syncthreads();
    #pragma unroll
    for (int it = 0; it < 8; it++) {
        int idx = tid + it*256;
        int l = idx >> 6, v = idx & 63;
        float acc = 0.f;
        #pragma unroll
        for (int kk = 0; kk < Lv; kk++)
            acc += s_left[l][kk] * s_y[kk][v];
        out[((size_t)bh*kS + (size_t)l*BSv + j)*kD + v] = acc;
    }
}

// ---------------- launch ----------------
extern "C" void kernel_launch(void* const* d_in, const int* in_sizes, int n_in,
                              void* d_out, int out_size) {
    (void)in_sizes; (void)n_in; (void)out_size;
    const float* q      = (const float*)d_in[0];
    const float* key    = (const float*)d_in[1];
    const float* val    = (const float*)d_in[2];
    const float* ascale = (const float*)d_in[3];
    const float* ssz    = (const float*)d_in[4];
    float* out = (float*)d_out;

    const size_t SMEM_C = (size_t)SMEM_C_FLOATS * sizeof(float);
    cudaFuncSetAttribute(right_step_kernel<0>, cudaFuncAttributeMaxDynamicSharedMemorySize, (int)SMEM_C);
    cudaFuncSetAttribute(right_step_kernel<1>, cudaFuncAttributeMaxDynamicSharedMemorySize, (int)SMEM_C);

    int nq_blocks = (BH*kS*kD) / 256;
    prep_kernel<<<nq_blocks, 256>>>(q, ascale, ssz);
    init_kr_kernel<<<BH*Lv, 256>>>(key);
    for (int s = 0; s < NSTEPS; s++) {
        if (s < NSTEPS-1) {
            left_step_kernel<false><<<BH*BSv, 256>>>(s);
            right_step_kernel<0><<<BH*Lv, 256, SMEM_C>>>(key, val, s);
        } else {
            left_step_kernel<true><<<BH*BSv, 256>>>(s);
            right_step_kernel<1><<<BH*Lv, 256, SMEM_C>>>(key, val, s);
        }
    }
    zout_kernel<<<BH*BSv, 256>>>(out);
}

// round 4
// speedup vs baseline: 1.3773x; 1.3763x over previous
#include <cuda_runtime.h>
#include <math.h>
#include <stdint.h>

// Shapes (fixed for this problem)
#define kB 4
#define kH 12
#define kS 2048
#define kD 64
#define BSv 64
#define Lv 32
#define NSTEPS 4
#define BH (kB*kH)

// ---------------- device scratch (module-load allocated) ----------------
__device__ float g_lp[(size_t)BH*BSv*Lv*Lv];      // [bh][j][l][k]
__device__ float g_rp[(size_t)BH*Lv*BSv*BSv];     // [bh][k][j][i]
__device__ float g_KR[(size_t)BH*Lv*BSv*kD];      // [bh][k][j][v]  (reused as Y at the end)
__device__ float g_LQ[(size_t)BH*BSv*Lv*kD];      // [bh][j][kk][v]
__device__ float g_r2[BH*Lv*BSv];                 // [bh][k][j]
__device__ float g_l2[BH*BSv*Lv];                 // [bh][j][k]
__device__ float g_leftF[(size_t)BH*BSv*Lv*Lv];   // final left [bh][j][l][k]
__device__ float g_eta[kH*2*NSTEPS];              // softplus(step_size)
__device__ float g_asc[kH];                       // softplus(attention_scale)/sqrt(D)

__device__ __forceinline__ float softplusf(float x) {
    return x > 20.f ? x : log1pf(expf(x));
}

// reduce over the 16-lane tx group (lanes 0-15 / 16-31 independently)
__device__ __forceinline__ float rsum16(float v) {
    v += __shfl_xor_sync(0xffffffffu, v, 8);
    v += __shfl_xor_sync(0xffffffffu, v, 4);
    v += __shfl_xor_sync(0xffffffffu, v, 2);
    v += __shfl_xor_sync(0xffffffffu, v, 1);
    return v;
}

__device__ __forceinline__ void cp_async16(uint32_t smem_addr, const void* gptr) {
    asm volatile("cp.async.cg.shared.global [%0], [%1], 16;"
                 :: "r"(smem_addr), "l"(gptr) : "memory");
}
__device__ __forceinline__ void cp_async_commit() {
    asm volatile("cp.async.commit_group;" ::: "memory");
}
__device__ __forceinline__ void cp_async_wait0() {
    asm volatile("cp.async.wait_group 0;" ::: "memory");
}

// ---------------- prep: lp/rp init, eta, asc ----------------
__global__ void __launch_bounds__(256) prep_kernel(const float* __restrict__ ascale,
                                                   const float* __restrict__ ssize) {
    size_t i = (size_t)blockIdx.x * 256 + threadIdx.x;
    size_t stride = (size_t)gridDim.x * 256;
    const size_t LPN = (size_t)BH*BSv*Lv*Lv;
    const size_t RPN = (size_t)BH*Lv*BSv*BSv;
    for (size_t t = i; t < LPN; t += stride) g_lp[t] = 0.17677669529663687f;   // 1/sqrt(32)
    for (size_t t = i; t < RPN; t += stride) g_rp[t] = 0.125f;                  // 1/sqrt(64)
    if (i < (size_t)kH*2*NSTEPS) g_eta[i] = softplusf(ssize[i]);
    if (i < kH) g_asc[i] = softplusf(ascale[i]) * 0.125f;                       // 1/sqrt(64)
}

// ---------------- step-0 KR: right0 == 1/64 -> KR0 = colmean of K ----------------
__global__ void __launch_bounds__(256) init_kr_kernel(const float* __restrict__ key) {
    int bh = blockIdx.x / Lv;
    int k  = blockIdx.x % Lv;
    const float* Kt = key + ((size_t)bh*kS + (size_t)k*BSv) * kD;
    __shared__ float s_m[kD];
    int tid = threadIdx.x;
    if (tid < kD) {
        float s = 0.f;
        #pragma unroll 8
        for (int i = 0; i < BSv; i++) s += Kt[(size_t)i*kD + tid];
        s_m[tid] = s * (1.0f/64.0f);
    }
    __syncthreads();
    float* KRo = g_KR + ((size_t)(bh*Lv + k) * BSv) * kD;
    #pragma unroll
    for (int it = 0; it < (BSv*kD)/256; it++) {
        int idx = tid + it*256;
        KRo[idx] = s_m[idx & 63];
    }
    if (tid < BSv) g_r2[(bh*Lv + k)*BSv + tid] = 1.0f/64.0f;
}

// ---------------- left step: per (bh, j), fused ----------------
// smem: s_lp[32*32], s_left[32*32], s_qT[64][34], s_krT[64][34], s_q[32][64], s_r2c[32]
template<bool LAST>
__global__ void __launch_bounds__(256) left_step_kernel(const float* __restrict__ query, int s) {
    __shared__ float s_lp[Lv*Lv];
    __shared__ float s_left[Lv*Lv];
    __shared__ float s_qT[kD][Lv + 2];
    __shared__ float s_krT[kD][Lv + 2];
    __shared__ float s_q[Lv][kD];
    __shared__ float s_r2c[Lv];

    int bh = blockIdx.x / BSv;
    int j  = blockIdx.x % BSv;
    int h  = bh % kH;
    int tid = threadIdx.x;
    int tx = tid & 15;        // k-tile index
    int ty = tid >> 4;        // l-tile index

    const size_t lp_base = ((size_t)(bh*BSv + j)) * (Lv*Lv);
    #pragma unroll
    for (int it = 0; it < 4; it++) {
        int idx = tid + it*256;
        s_lp[idx] = g_lp[lp_base + idx];
    }
    if (tid < Lv) s_r2c[tid] = g_r2[(bh*Lv + tid)*BSv + j];

    // load Q (scaled) and KR: 512 float4 loads
    float qsc = g_asc[h];
    const float* KRb = g_KR + (size_t)bh*Lv*BSv*kD;
    #pragma unroll
    for (int it = 0; it < 2; it++) {
        int idx = tid + it*256;            // 0..511
        int row = idx >> 4;                // l  0..31
        int vq  = (idx & 15) * 4;          // v
        size_t goff = ((size_t)bh*kS + (size_t)row*BSv + j)*kD + vq;
        float4 q4 = *(const float4*)&query[goff];
        q4.x *= qsc; q4.y *= qsc; q4.z *= qsc; q4.w *= qsc;
        *(float4*)&s_q[row][vq] = q4;
        s_qT[vq+0][row] = q4.x; s_qT[vq+1][row] = q4.y;
        s_qT[vq+2][row] = q4.z; s_qT[vq+3][row] = q4.w;
        float4 kr4 = *(const float4*)&KRb[((size_t)row*BSv + j)*kD + vq];
        s_krT[vq+0][row] = kr4.x; s_krT[vq+1][row] = kr4.y;
        s_krT[vq+2][row] = kr4.z; s_krT[vq+3][row] = kr4.w;
    }
    __syncthreads();

    // t2l[l][k] in registers: 2x2 tiles, l0=ty*2, k0=tx*2
    int l0 = ty*2, k0 = tx*2;
    float a00=0.f,a01=0.f,a10=0.f,a11=0.f;
    #pragma unroll
    for (int v = 0; v < kD; v++) {
        float2 a = *(const float2*)&s_qT[v][l0];
        float2 b = *(const float2*)&s_krT[v][k0];
        a00 += a.x*b.x; a01 += a.x*b.y;
        a10 += a.y*b.x; a11 += a.y*b.y;
    }

    // fused: normalize lp row, dl, project, update; store left (pre-update)
    float eta = g_eta[h*(2*NSTEPS) + s];
    float r2c0 = s_r2c[k0], r2c1 = s_r2c[k0+1];
    #pragma unroll
    for (int r = 0; r < 2; r++) {
        int lr = l0 + r;
        float2 lp2 = *(const float2*)&s_lp[lr*Lv + k0];
        float ss = rsum16(lp2.x*lp2.x + lp2.y*lp2.y);
        float n  = sqrtf(ss);
        float sc   = n > 0.f ? 1.0f/n : 1.0f;
        float invn = n > 0.f ? 1.0f/n : 0.0f;
        float ls0 = lp2.x*sc, ls1 = lp2.y*sc;
        float le0 = ls0*ls0,  le1 = ls1*ls1;
        *(float2*)&s_left[lr*Lv + k0] = make_float2(le0, le1);
        float t0 = (r==0) ? a00 : a10;
        float t1 = (r==0) ? a01 : a11;
        float dl0 = (r2c0*le0 - t0) * 2.f * ls0;
        float dl1 = (r2c1*le1 - t1) * 2.f * ls1;
        float dot = rsum16(ls0*dl0 + ls1*dl1);
        dl0 = (dl0 - ls0*dot) * invn;
        dl1 = (dl1 - ls1*dot) * invn;
        float np0 = lp2.x - eta*dl0;
        float np1 = lp2.y - eta*dl1;
        if (!LAST) {
            *(float2*)&g_lp[lp_base + lr*Lv + k0] = make_float2(np0, np1);
        } else {
            float ss2 = rsum16(np0*np0 + np1*np1);
            float n2  = sqrtf(ss2);
            float sc2 = n2 > 0.f ? 1.0f/n2 : 1.0f;
            float f0 = np0*sc2, f1 = np1*sc2;
            *(float2*)&g_leftF[lp_base + lr*Lv + k0] = make_float2(f0*f0, f1*f1);
        }
    }
    __syncthreads();

    // l2[k] = sum_l left^2
    if (tid < Lv) {
        float acc = 0.f;
        #pragma unroll
        for (int l = 0; l < Lv; l++) { float v = s_left[l*Lv + tid]; acc += v*v; }
        g_l2[(size_t)(bh*BSv + j)*Lv + tid] = acc;
    }

    // LQ[kk][v] = sum_l left[l][kk]*q[l][v] : 2x4 tiles (kk0=ty*2, v0=tx*4)
    {
        int kk0 = ty*2, v0 = tx*4;
        float acc0[4] = {}, acc1[4] = {};
        #pragma unroll
        for (int l = 0; l < Lv; l++) {
            float a0 = s_left[l*Lv + kk0];
            float a1 = s_left[l*Lv + kk0 + 1];
            float4 b4 = *(const float4*)&s_q[l][v0];
            acc0[0] += a0*b4.x; acc0[1] += a0*b4.y; acc0[2] += a0*b4.z; acc0[3] += a0*b4.w;
            acc1[0] += a1*b4.x; acc1[1] += a1*b4.y; acc1[2] += a1*b4.z; acc1[3] += a1*b4.w;
        }
        float* LQo = g_LQ + ((size_t)(bh*BSv + j)) * Lv * kD;
        *(float4*)&LQo[(size_t)kk0*kD + v0]     = make_float4(acc0[0],acc0[1],acc0[2],acc0[3]);
        *(float4*)&LQo[(size_t)(kk0+1)*kD + v0] = make_float4(acc1[0],acc1[1],acc1[2],acc1[3]);
    }
}

// ---------------- right step: per (bh, k), fused ----------------
#define C_PAD 68
#define SMEM_R_FLOATS (4096 + 4352 + 4352 + 64)

template<int MODE>  // 0 = update rp + compute next KR/r2 ; 1 = last step: compute Y from V
__global__ void __launch_bounds__(256, 4) right_step_kernel(const float* __restrict__ key,
                                                            const float* __restrict__ val,
                                                            int s) {
    extern __shared__ float sm[];
    float* s_rs   = sm;                  // 64x64 raw rp
    float* s_KT   = s_rs  + 4096;        // [v][i] stride 68; later rightT[i][j] stride 68
    float* s_LQT  = s_KT  + 4352;        // [v][j] stride 68; later Km row-major (4096 used)
    float* s_l2   = s_LQT + 4352;        // 64

    int bh = blockIdx.x / Lv;
    int k  = blockIdx.x % Lv;
    int h  = bh % kH;
    int tid = threadIdx.x;
    int tx = tid & 15;
    int ty = tid >> 4;
    int j0 = ty*4, i0 = tx*4;

    const size_t rp_base = ((size_t)(bh*Lv + k)) * (BSv*BSv);
    const float* Kt  = key + ((size_t)bh*kS + (size_t)k*BSv) * kD;
    const float* Vt  = val + ((size_t)bh*kS + (size_t)k*BSv) * kD;
    const float* LQb = g_LQ + (size_t)bh*BSv*Lv*kD + (size_t)k*kD;

    #pragma unroll
    for (int it = 0; it < 16; it++) {
        int idx = tid + it*256;
        s_rs[idx] = g_rp[rp_base + idx];
        int row = idx >> 6, v = idx & 63;
        s_KT[v*C_PAD + row]  = Kt[idx];
        s_LQT[v*C_PAD + row] = LQb[(size_t)row*(Lv*kD) + v];
    }
    if (tid < BSv) s_l2[tid] = g_l2[(size_t)(bh*BSv + tid)*Lv + k];
    __syncthreads();

    // GEMM1: t2r[j][i] = sum_v LQ[j][v]*K[i][v]  (registers, 4x4 tiles)
    float acc[4][4] = {};
    #pragma unroll
    for (int v = 0; v < kD; v++) {
        float4 a4 = *(const float4*)&s_LQT[v*C_PAD + j0];
        float4 b4 = *(const float4*)&s_KT[v*C_PAD + i0];
        float a[4] = {a4.x,a4.y,a4.z,a4.w};
        float b[4] = {b4.x,b4.y,b4.z,b4.w};
        #pragma unroll
        for (int r = 0; r < 4; r++)
            #pragma unroll
            for (int c = 0; c < 4; c++)
                acc[r][c] += a[r]*b[c];
    }
    __syncthreads();   // everyone done reading s_KT / s_LQT

    // prefetch Km (K for MODE0, V for MODE1) into s_LQT region via cp.async,
    // overlapped with the fused dr phase below
    {
        uint32_t sdst = (uint32_t)__cvta_generic_to_shared(s_LQT);
        const float4* Gp = (const float4*)(MODE == 0 ? Kt : Vt);
        #pragma unroll
        for (int it = 0; it < 4; it++) {
            int idx = tid + it*256;          // 0..1023 float4s
            cp_async16(sdst + (uint32_t)idx*16, Gp + idx);
        }
        cp_async_commit();
    }

    // fused dr: normalize rp row, grad, project, update, renormalize; rightT -> s_KT
    float eta = g_eta[h*(2*NSTEPS) + NSTEPS + s];
    #pragma unroll
    for (int r = 0; r < 4; r++) {
        int jr = j0 + r;
        float4 rp4 = *(const float4*)&s_rs[jr*BSv + i0];
        float ss = rsum16(rp4.x*rp4.x + rp4.y*rp4.y + rp4.z*rp4.z + rp4.w*rp4.w);
        float n  = sqrtf(ss);
        float sc   = n > 0.f ? 1.0f/n : 1.0f;
        float invn = n > 0.f ? 1.0f/n : 0.0f;
        float rs0 = rp4.x*sc, rs1 = rp4.y*sc, rs2 = rp4.z*sc, rs3 = rp4.w*sc;
        float l2v = s_l2[jr];
        float dr0 = (l2v*rs0*rs0 - acc[r][0]) * 2.f * rs0;
        float dr1 = (l2v*rs1*rs1 - acc[r][1]) * 2.f * rs1;
        float dr2 = (l2v*rs2*rs2 - acc[r][2]) * 2.f * rs2;
        float dr3 = (l2v*rs3*rs3 - acc[r][3]) * 2.f * rs3;
        float dot = rsum16(rs0*dr0 + rs1*dr1 + rs2*dr2 + rs3*dr3);
        dr0 = (dr0 - rs0*dot) * invn;
        dr1 = (dr1 - rs1*dot) * invn;
        dr2 = (dr2 - rs2*dot) * invn;
        dr3 = (dr3 - rs3*dot) * invn;
        float np0 = rp4.x - eta*dr0;
        float np1 = rp4.y - eta*dr1;
        float np2 = rp4.z - eta*dr2;
        float np3 = rp4.w - eta*dr3;
        if (MODE == 0) {
            *(float4*)&g_rp[rp_base + (size_t)jr*BSv + i0] = make_float4(np0,np1,np2,np3);
        }
        float ss2 = rsum16(np0*np0 + np1*np1 + np2*np2 + np3*np3);
        float n2  = sqrtf(ss2);
        float sc2 = n2 > 0.f ? 1.0f/n2 : 1.0f;
        float rn0 = np0*sc2, rn1 = np1*sc2, rn2 = np2*sc2, rn3 = np3*sc2;
        float rt0 = rn0*rn0, rt1 = rn1*rn1, rt2 = rn2*rn2, rt3 = rn3*rn3;
        // rightT[i][j] into s_KT region (stride 68)
        s_KT[(i0+0)*C_PAD + jr] = rt0;
        s_KT[(i0+1)*C_PAD + jr] = rt1;
        s_KT[(i0+2)*C_PAD + jr] = rt2;
        s_KT[(i0+3)*C_PAD + jr] = rt3;
        if (MODE == 0) {
            float r2s = rsum16(rt0*rt0 + rt1*rt1 + rt2*rt2 + rt3*rt3);
            if (tx == 0) g_r2[(bh*Lv + k)*BSv + jr] = r2s;
        }
    }
    cp_async_wait0();
    __syncthreads();

    // GEMM2: OUT[j][v] = sum_i rightT[i][j] * Km[i][v]  -> g_KR (next KR, or Y)
    float* outp = g_KR + ((size_t)(bh*Lv + k) * BSv) * kD;
    {
        int v0 = tx*4;
        float acc2[4][4] = {};
        #pragma unroll
        for (int i = 0; i < BSv; i++) {
            float4 a4 = *(const float4*)&s_KT[i*C_PAD + j0];
            float4 b4 = *(const float4*)&s_LQT[i*kD + v0];
            float a[4] = {a4.x,a4.y,a4.z,a4.w};
            float b[4] = {b4.x,b4.y,b4.z,b4.w};
            #pragma unroll
            for (int r = 0; r < 4; r++)
                #pragma unroll
                for (int c = 0; c < 4; c++)
                    acc2[r][c] += a[r]*b[c];
        }
        #pragma unroll
        for (int r = 0; r < 4; r++)
            *(float4*)&outp[(size_t)(j0+r)*kD + v0] =
                make_float4(acc2[r][0],acc2[r][1],acc2[r][2],acc2[r][3]);
    }
}

// ---------------- final Z = left @ Y, scatter to output ----------------
__global__ void __launch_bounds__(256) zout_kernel(float* __restrict__ out) {
    __shared__ float s_left[Lv][Lv];
    __shared__ float s_y[Lv][kD];
    int bh = blockIdx.x / BSv;
    int j  = blockIdx.x % BSv;
    int tid = threadIdx.x;
    size_t lbase = ((size_t)(bh*BSv + j)) * (Lv*Lv);
    #pragma unroll
    for (int it = 0; it < 4; it++) {
        int idx = tid + it*256;
        ((float*)s_left)[idx] = g_leftF[lbase + idx];
    }
    const float* Yb = g_KR + (size_t)bh*Lv*BSv*kD + (size_t)j*kD;
    #pragma unroll
    for (int it = 0; it < 8; it++) {
        int idx = tid + it*256;
        int kk = idx >> 6, v = idx & 63;
        s_y[kk][v] = Yb[(size_t)kk*(BSv*kD) + v];
    }
    __syncthreads();
    // 1x8 outputs per thread done as 2x4 tiles: l0=ty*2, v0=tx*4
    int tx = tid & 15, ty = tid >> 4;
    int l00 = ty*2, v0 = tx*4;
    float acc0[4] = {}, acc1[4] = {};
    #pragma unroll
    for (int kk = 0; kk < Lv; kk++) {
        float a0 = s_left[l00][kk];
        float a1 = s_left[l00+1][kk];
        float4 b4 = *(const float4*)&s_y[kk][v0];
        acc0[0] += a0*b4.x; acc0[1] += a0*b4.y; acc0[2] += a0*b4.z; acc0[3] += a0*b4.w;
        acc1[0] += a1*b4.x; acc1[1] += a1*b4.y; acc1[2] += a1*b4.z; acc1[3] += a1*b4.w;
    }
    *(float4*)&out[((size_t)bh*kS + (size_t)l00*BSv + j)*kD + v0] =
        make_float4(acc0[0],acc0[1],acc0[2],acc0[3]);
    *(float4*)&out[((size_t)bh*kS + (size_t)(l00+1)*BSv + j)*kD + v0] =
        make_float4(acc1[0],acc1[1],acc1[2],acc1[3]);
}

// ---------------- launch ----------------
extern "C" void kernel_launch(void* const* d_in, const int* in_sizes, int n_in,
                              void* d_out, int out_size) {
    (void)in_sizes; (void)n_in; (void)out_size;
    const float* q      = (const float*)d_in[0];
    const float* key    = (const float*)d_in[1];
    const float* val    = (const float*)d_in[2];
    const float* ascale = (const float*)d_in[3];
    const float* ssz    = (const float*)d_in[4];
    float* out = (float*)d_out;

    const size_t SMEM_R = (size_t)SMEM_R_FLOATS * sizeof(float);
    cudaFuncSetAttribute(right_step_kernel<0>, cudaFuncAttributeMaxDynamicSharedMemorySize, (int)SMEM_R);
    cudaFuncSetAttribute(right_step_kernel<1>, cudaFuncAttributeMaxDynamicSharedMemorySize, (int)SMEM_R);

    prep_kernel<<<4096, 256>>>(ascale, ssz);
    init_kr_kernel<<<BH*Lv, 256>>>(key);
    for (int s = 0; s < NSTEPS; s++) {
        if (s < NSTEPS-1) {
            left_step_kernel<false><<<BH*BSv, 256>>>(q, s);
            right_step_kernel<0><<<BH*Lv, 256, SMEM_R>>>(key, val, s);
        } else {
            left_step_kernel<true><<<BH*BSv, 256>>>(q, s);
            right_step_kernel<1><<<BH*Lv, 256, SMEM_R>>>(key, val, s);
        }
    }
    zout_kernel<<<BH*BSv, 256>>>(out);
}

// round 5
// speedup vs baseline: 1.5569x; 1.1304x over previous
#include <cuda_runtime.h>
#include <math.h>
#include <stdint.h>

// Shapes (fixed for this problem)
#define kB 4
#define kH 12
#define kS 2048
#define kD 64
#define BSv 64
#define Lv 32
#define NSTEPS 4
#define BH (kB*kH)

typedef unsigned long long ull;

// ---------------- device scratch (module-load allocated) ----------------
__device__ float g_lp[(size_t)BH*BSv*Lv*Lv];      // [bh][j][l][k]
__device__ float g_rp[(size_t)BH*Lv*BSv*BSv];     // [bh][k][j][i]
__device__ float g_KR[(size_t)BH*Lv*BSv*kD];      // [bh][k][j][v]  (reused as Y at the end)
__device__ float g_LQ[(size_t)BH*BSv*Lv*kD];      // [bh][j][kk][v]
__device__ float g_r2[BH*Lv*BSv];                 // [bh][k][j]
__device__ float g_l2[BH*BSv*Lv];                 // [bh][j][k]
__device__ float g_leftF[(size_t)BH*BSv*Lv*Lv];   // final left [bh][j][l][k]
__device__ float g_eta[kH*2*NSTEPS];              // softplus(step_size)
__device__ float g_asc[kH];                       // softplus(attention_scale)/sqrt(D)

__device__ __forceinline__ float softplusf(float x) {
    return x > 20.f ? x : log1pf(expf(x));
}

// reduce over the 16-lane tx group (lanes 0-15 / 16-31 independently)
__device__ __forceinline__ float rsum16(float v) {
    v += __shfl_xor_sync(0xffffffffu, v, 8);
    v += __shfl_xor_sync(0xffffffffu, v, 4);
    v += __shfl_xor_sync(0xffffffffu, v, 2);
    v += __shfl_xor_sync(0xffffffffu, v, 1);
    return v;
}

// ---- packed f32x2 helpers (FFMA2) ----
__device__ __forceinline__ ull pdup(float x) {
    ull r; asm("mov.b64 %0, {%1, %1};" : "=l"(r) : "f"(x)); return r;
}
__device__ __forceinline__ float2 up2(ull v) {
    float2 r; asm("mov.b64 {%0, %1}, %2;" : "=f"(r.x), "=f"(r.y) : "l"(v)); return r;
}
__device__ __forceinline__ void fma2(ull &d, ull a, ull b) {
    asm("fma.rn.f32x2 %0, %1, %2, %0;" : "+l"(d) : "l"(a), "l"(b));
}

__device__ __forceinline__ void cp_async16(uint32_t smem_addr, const void* gptr) {
    asm volatile("cp.async.cg.shared.global [%0], [%1], 16;"
                 :: "r"(smem_addr), "l"(gptr) : "memory");
}
__device__ __forceinline__ void cp_async_commit() {
    asm volatile("cp.async.commit_group;" ::: "memory");
}
__device__ __forceinline__ void cp_async_wait0() {
    asm volatile("cp.async.wait_group 0;" ::: "memory");
}

// ---------------- prep: eta, asc only (lp/rp handled by INIT kernels) ----------------
__global__ void __launch_bounds__(128) prep_kernel(const float* __restrict__ ascale,
                                                   const float* __restrict__ ssize) {
    int i = threadIdx.x;
    if (i < kH*2*NSTEPS) g_eta[i] = softplusf(ssize[i]);
    if (i < kH) g_asc[i] = softplusf(ascale[i]) * 0.125f;   // 1/sqrt(64)
}

// ---------------- step-0 KR: right0 == 1/64 -> KR0 = colmean of K ----------------
__global__ void __launch_bounds__(256) init_kr_kernel(const float* __restrict__ key) {
    int bh = blockIdx.x / Lv;
    int k  = blockIdx.x % Lv;
    const float* Kt = key + ((size_t)bh*kS + (size_t)k*BSv) * kD;
    __shared__ float s_m[kD];
    int tid = threadIdx.x;
    if (tid < kD) {
        float s = 0.f;
        #pragma unroll 8
        for (int i = 0; i < BSv; i++) s += Kt[(size_t)i*kD + tid];
        s_m[tid] = s * (1.0f/64.0f);
    }
    __syncthreads();
    float* KRo = g_KR + ((size_t)(bh*Lv + k) * BSv) * kD;
    #pragma unroll
    for (int it = 0; it < (BSv*kD)/256; it++) {
        int idx = tid + it*256;
        KRo[idx] = s_m[idx & 63];
    }
}

// ---------------- left step: per (bh, j), fused, FFMA2 ----------------
// Transposed arrays use XOR swizzle: phys(l, v) = v*32 + (l ^ (((v>>1)&15)<<1))
template<bool INIT, bool LAST>
__global__ void __launch_bounds__(256) left_step_kernel(const float* __restrict__ query, int s) {
    __shared__ float s_left[Lv*Lv];
    __shared__ float s_qT[kD*Lv];
    __shared__ float s_krT[kD*Lv];
    __shared__ float s_q[Lv*kD];
    __shared__ float s_r2c[Lv];

    int bh = blockIdx.x / BSv;
    int j  = blockIdx.x % BSv;
    int h  = bh % kH;
    int tid = threadIdx.x;
    int tx = tid & 15;        // k-tile index
    int ty = tid >> 4;        // l-tile index

    // load Q (scaled) and KR; build row-major s_q and swizzled transposes
    float qsc = g_asc[h];
    const float* KRb = g_KR + (size_t)bh*Lv*BSv*kD;
    #pragma unroll
    for (int it = 0; it < 2; it++) {
        int idx = tid + it*256;            // 0..511 float4s
        int row = idx >> 4;                // l  0..31
        int m   = idx & 15;
        int vq  = m*4;
        size_t goff = ((size_t)bh*kS + (size_t)row*BSv + j)*kD + vq;
        float4 q4 = *(const float4*)&query[goff];
        q4.x *= qsc; q4.y *= qsc; q4.z *= qsc; q4.w *= qsc;
        *(float4*)&s_q[row*kD + vq] = q4;
        float4 kr4 = *(const float4*)&KRb[((size_t)row*BSv + j)*kD + vq];
        float qv[4] = {q4.x,q4.y,q4.z,q4.w};
        float kv[4] = {kr4.x,kr4.y,kr4.z,kr4.w};
        #pragma unroll
        for (int t = 0; t < 4; t++) {
            int v  = vq + t;
            int sl = row ^ (((v>>1)&15)<<1);
            s_qT [v*Lv + sl] = qv[t];
            s_krT[v*Lv + sl] = kv[t];
        }
    }
    if (!INIT && tid < Lv) s_r2c[tid] = g_r2[(bh*Lv + tid)*BSv + j];
    __syncthreads();

    // t2l[l][k] in registers: rows l0,l0+1 ; k-pair k0,k0+1 (packed f32x2)
    int l0 = ty*2, k0 = tx*2;
    ull accA = 0ull, accB = 0ull;
    #pragma unroll
    for (int v = 0; v < kD; v++) {
        int X = ((v>>1)&15)<<1;
        float2 a = *(const float2*)&s_qT[v*Lv + (l0^X)];
        ull b = *(const ull*)&s_krT[v*Lv + (k0^X)];
        fma2(accA, pdup(a.x), b);
        fma2(accB, pdup(a.y), b);
    }
    float2 t2l0 = up2(accA), t2l1 = up2(accB);

    // fused: normalize lp row, dl, project, update; store left (pre-update)
    float eta = g_eta[h*(2*NSTEPS) + s];
    float r2c0 = INIT ? 0.015625f : s_r2c[k0];
    float r2c1 = INIT ? 0.015625f : s_r2c[k0+1];
    const size_t lp_base = ((size_t)(bh*BSv + j)) * (Lv*Lv);
    #pragma unroll
    for (int r = 0; r < 2; r++) {
        int lr = l0 + r;
        float2 lp2;
        if (INIT) lp2 = make_float2(0.17677669529663687f, 0.17677669529663687f);
        else      lp2 = *(const float2*)&g_lp[lp_base + lr*Lv + k0];
        float ss = rsum16(lp2.x*lp2.x + lp2.y*lp2.y);
        float n  = sqrtf(ss);
        float sc   = n > 0.f ? 1.0f/n : 1.0f;
        float invn = n > 0.f ? 1.0f/n : 0.0f;
        float ls0 = lp2.x*sc, ls1 = lp2.y*sc;
        float le0 = ls0*ls0,  le1 = ls1*ls1;
        *(float2*)&s_left[lr*Lv + k0] = make_float2(le0, le1);
        float t0 = (r==0) ? t2l0.x : t2l1.x;
        float t1 = (r==0) ? t2l0.y : t2l1.y;
        float dl0 = (r2c0*le0 - t0) * 2.f * ls0;
        float dl1 = (r2c1*le1 - t1) * 2.f * ls1;
        float dot = rsum16(ls0*dl0 + ls1*dl1);
        dl0 = (dl0 - ls0*dot) * invn;
        dl1 = (dl1 - ls1*dot) * invn;
        float np0 = lp2.x - eta*dl0;
        float np1 = lp2.y - eta*dl1;
        if (!LAST) {
            *(float2*)&g_lp[lp_base + lr*Lv + k0] = make_float2(np0, np1);
        } else {
            float ss2 = rsum16(np0*np0 + np1*np1);
            float n2  = sqrtf(ss2);
            float sc2 = n2 > 0.f ? 1.0f/n2 : 1.0f;
            float f0 = np0*sc2, f1 = np1*sc2;
            *(float2*)&g_leftF[lp_base + lr*Lv + k0] = make_float2(f0*f0, f1*f1);
        }
    }
    __syncthreads();

    // l2[k] = sum_l left^2
    if (tid < Lv) {
        float acc = 0.f;
        #pragma unroll
        for (int l = 0; l < Lv; l++) { float vv = s_left[l*Lv + tid]; acc += vv*vv; }
        g_l2[(size_t)(bh*BSv + j)*Lv + tid] = acc;
    }

    // LQ[kk][v] = sum_l left[l][kk]*q[l][v] : kk pair ty*2, v0=tx*4, FFMA2
    {
        int kk0 = ty*2, v0 = tx*4;
        ull a0p0=0ull, a0p1=0ull, a1p0=0ull, a1p1=0ull;
        #pragma unroll
        for (int l = 0; l < Lv; l++) {
            float2 a = *(const float2*)&s_left[l*Lv + kk0];
            ulonglong2 b = *(const ulonglong2*)&s_q[l*kD + v0];
            ull ad0 = pdup(a.x), ad1 = pdup(a.y);
            fma2(a0p0, ad0, b.x); fma2(a0p1, ad0, b.y);
            fma2(a1p0, ad1, b.x); fma2(a1p1, ad1, b.y);
        }
        float* LQo = g_LQ + ((size_t)(bh*BSv + j)) * Lv * kD;
        float2 r00 = up2(a0p0), r01 = up2(a0p1), r10 = up2(a1p0), r11 = up2(a1p1);
        *(float4*)&LQo[(size_t)kk0*kD + v0]     = make_float4(r00.x,r00.y,r01.x,r01.y);
        *(float4*)&LQo[(size_t)(kk0+1)*kD + v0] = make_float4(r10.x,r10.y,r11.x,r11.y);
    }
}

// ---------------- right step: per (bh, k), fused, FFMA2 ----------------
// Transposed arrays use XOR swizzle: phys(i, v) = v*64 + (i ^ (((v>>2)&7)<<2))
#define SMEM_RT_FLOATS (4096*3 + 64)

template<bool INIT, int MODE>  // MODE 0 = update rp + next KR/r2 ; 1 = last step: Y from V
__global__ void __launch_bounds__(256, 4) right_step_kernel(const float* __restrict__ key,
                                                            const float* __restrict__ val,
                                                            int s) {
    extern __shared__ float sm[];
    float* s_KT  = sm;            // swizzled [v][i]; later swizzled rightT [i][j]
    float* s_LQT = sm + 4096;     // swizzled [v][j]
    float* s_Km  = sm + 8192;     // row-major K (MODE0) or V (MODE1), cp.async
    float* s_l2  = sm + 12288;    // 64

    int bh = blockIdx.x / Lv;
    int k  = blockIdx.x % Lv;
    int h  = bh % kH;
    int tid = threadIdx.x;
    int tx = tid & 15;
    int ty = tid >> 4;
    int j0 = ty*4, i0 = tx*4;

    const size_t rp_base = ((size_t)(bh*Lv + k)) * (BSv*BSv);
    const float* Kt  = key + ((size_t)bh*kS + (size_t)k*BSv) * kD;
    const float* Vt  = val + ((size_t)bh*kS + (size_t)k*BSv) * kD;
    const float* LQb = g_LQ + (size_t)bh*BSv*Lv*kD + (size_t)k*kD;

    // kick off Km (K or V) prefetch immediately — hidden behind everything up to GEMM2
    {
        uint32_t sdst = (uint32_t)__cvta_generic_to_shared(s_Km);
        const float4* Gp = (const float4*)(MODE == 0 ? Kt : Vt);
        #pragma unroll
        for (int it = 0; it < 4; it++) {
            int idx = tid + it*256;          // 0..1023 float4s
            cp_async16(sdst + (uint32_t)idx*16, Gp + idx);
        }
        cp_async_commit();
    }

    // load K and LQ, transposed+swizzled (xor offset constant per thread)
    #pragma unroll
    for (int it = 0; it < 4; it++) {
        int idx = tid + it*256;        // 0..1023 float4s
        int row = idx >> 4;            // i or j: 0..63
        int m   = idx & 15;
        int vq  = m*4;
        int sr  = row ^ ((m & 7) << 2);
        float4 k4 = *(const float4*)&Kt[(size_t)row*kD + vq];
        float4 l4 = *(const float4*)&LQb[(size_t)row*(Lv*kD) + vq];
        s_KT [(vq+0)*BSv + sr] = k4.x; s_KT [(vq+1)*BSv + sr] = k4.y;
        s_KT [(vq+2)*BSv + sr] = k4.z; s_KT [(vq+3)*BSv + sr] = k4.w;
        s_LQT[(vq+0)*BSv + sr] = l4.x; s_LQT[(vq+1)*BSv + sr] = l4.y;
        s_LQT[(vq+2)*BSv + sr] = l4.z; s_LQT[(vq+3)*BSv + sr] = l4.w;
    }
    if (tid < BSv) s_l2[tid] = g_l2[(size_t)(bh*BSv + tid)*Lv + k];
    __syncthreads();

    // GEMM1: t2r[j][i] = sum_v LQ[j][v]*K[i][v]  (4x4 tiles, packed f32x2)
    ull acc[4][2] = {};
    #pragma unroll
    for (int v = 0; v < kD; v++) {
        int xo = ((v>>2)&7)<<2;
        float4 a4 = *(const float4*)&s_LQT[v*BSv + (j0^xo)];
        ulonglong2 b2 = *(const ulonglong2*)&s_KT[v*BSv + (i0^xo)];
        ull a0 = pdup(a4.x), a1 = pdup(a4.y), a2 = pdup(a4.z), a3 = pdup(a4.w);
        fma2(acc[0][0], a0, b2.x); fma2(acc[0][1], a0, b2.y);
        fma2(acc[1][0], a1, b2.x); fma2(acc[1][1], a1, b2.y);
        fma2(acc[2][0], a2, b2.x); fma2(acc[2][1], a2, b2.y);
        fma2(acc[3][0], a3, b2.x); fma2(acc[3][1], a3, b2.y);
    }
    __syncthreads();   // everyone done reading s_KT / s_LQT

    // fused dr: rp from gmem/const, grad, project, update, renorm; rightT -> s_KT (swizzled on i)
    float eta = g_eta[h*(2*NSTEPS) + NSTEPS + s];
    int sxo = (tx & 7) << 2;   // ((i0+c)>>2 & 7)<<2, constant over c
    #pragma unroll
    for (int r = 0; r < 4; r++) {
        int jr = j0 + r;
        float4 rp4 = INIT ? make_float4(0.125f, 0.125f, 0.125f, 0.125f)
                          : *(const float4*)&g_rp[rp_base + (size_t)jr*BSv + i0];
        float ss = rsum16(rp4.x*rp4.x + rp4.y*rp4.y + rp4.z*rp4.z + rp4.w*rp4.w);
        float n  = sqrtf(ss);
        float sc   = n > 0.f ? 1.0f/n : 1.0f;
        float invn = n > 0.f ? 1.0f/n : 0.0f;
        float rs0 = rp4.x*sc, rs1 = rp4.y*sc, rs2 = rp4.z*sc, rs3 = rp4.w*sc;
        float l2v = s_l2[jr];
        float2 t01 = up2(acc[r][0]);
        float2 t23 = up2(acc[r][1]);
        float dr0 = (l2v*rs0*rs0 - t01.x) * 2.f * rs0;
        float dr1 = (l2v*rs1*rs1 - t01.y) * 2.f * rs1;
        float dr2 = (l2v*rs2*rs2 - t23.x) * 2.f * rs2;
        float dr3 = (l2v*rs3*rs3 - t23.y) * 2.f * rs3;
        float dot = rsum16(rs0*dr0 + rs1*dr1 + rs2*dr2 + rs3*dr3);
        dr0 = (dr0 - rs0*dot) * invn;
        dr1 = (dr1 - rs1*dot) * invn;
        dr2 = (dr2 - rs2*dot) * invn;
        dr3 = (dr3 - rs3*dot) * invn;
        float np0 = rp4.x - eta*dr0;
        float np1 = rp4.y - eta*dr1;
        float np2 = rp4.z - eta*dr2;
        float np3 = rp4.w - eta*dr3;
        if (MODE == 0) {
            *(float4*)&g_rp[rp_base + (size_t)jr*BSv + i0] = make_float4(np0,np1,np2,np3);
        }
        float ss2 = rsum16(np0*np0 + np1*np1 + np2*np2 + np3*np3);
        float n2  = sqrtf(ss2);
        float sc2 = n2 > 0.f ? 1.0f/n2 : 1.0f;
        float rn0 = np0*sc2, rn1 = np1*sc2, rn2 = np2*sc2, rn3 = np3*sc2;
        float rt0 = rn0*rn0, rt1 = rn1*rn1, rt2 = rn2*rn2, rt3 = rn3*rn3;
        int sj = jr ^ sxo;
        s_KT[(i0+0)*BSv + sj] = rt0;
        s_KT[(i0+1)*BSv + sj] = rt1;
        s_KT[(i0+2)*BSv + sj] = rt2;
        s_KT[(i0+3)*BSv + sj] = rt3;
        if (MODE == 0) {
            float r2s = rsum16(rt0*rt0 + rt1*rt1 + rt2*rt2 + rt3*rt3);
            if (tx == 0) g_r2[(bh*Lv + k)*BSv + jr] = r2s;
        }
    }
    cp_async_wait0();
    __syncthreads();

    // GEMM2: OUT[j][v] = sum_i rightT[i][j] * Km[i][v]  -> g_KR (next KR, or Y)
    float* outp = g_KR + ((size_t)(bh*Lv + k) * BSv) * kD;
    {
        int v0 = tx*4;
        ull acc2[4][2] = {};
        #pragma unroll
        for (int i = 0; i < BSv; i++) {
            int xo = ((i>>2)&7)<<2;
            float4 a4 = *(const float4*)&s_KT[i*BSv + (j0^xo)];
            ulonglong2 b2 = *(const ulonglong2*)&s_Km[i*kD + v0];
            ull a0 = pdup(a4.x), a1 = pdup(a4.y), a2 = pdup(a4.z), a3 = pdup(a4.w);
            fma2(acc2[0][0], a0, b2.x); fma2(acc2[0][1], a0, b2.y);
            fma2(acc2[1][0], a1, b2.x); fma2(acc2[1][1], a1, b2.y);
            fma2(acc2[2][0], a2, b2.x); fma2(acc2[2][1], a2, b2.y);
            fma2(acc2[3][0], a3, b2.x); fma2(acc2[3][1], a3, b2.y);
        }
        #pragma unroll
        for (int r = 0; r < 4; r++) {
            float2 o01 = up2(acc2[r][0]);
            float2 o23 = up2(acc2[r][1]);
            *(float4*)&outp[(size_t)(j0+r)*kD + v0] = make_float4(o01.x,o01.y,o23.x,o23.y);
        }
    }
}

// ---------------- final Z = left @ Y, scatter to output ----------------
__global__ void __launch_bounds__(256) zout_kernel(float* __restrict__ out) {
    __shared__ float s_left[Lv*Lv];
    __shared__ float s_y[Lv*kD];
    int bh = blockIdx.x / BSv;
    int j  = blockIdx.x % BSv;
    int tid = threadIdx.x;
    size_t lbase = ((size_t)(bh*BSv + j)) * (Lv*Lv);
    #pragma unroll
    for (int it = 0; it < 4; it++) {
        int idx = tid + it*256;
        s_left[idx] = g_leftF[lbase + idx];
    }
    const float* Yb = g_KR + (size_t)bh*Lv*BSv*kD + (size_t)j*kD;
    #pragma unroll
    for (int it = 0; it < 8; it++) {
        int idx = tid + it*256;
        int kk = idx >> 6, v = idx & 63;
        s_y[kk*kD + v] = Yb[(size_t)kk*(BSv*kD) + v];
    }
    __syncthreads();
    int tx = tid & 15, ty = tid >> 4;
    int l00 = ty*2, v0 = tx*4;
    ull a0p0=0ull, a0p1=0ull, a1p0=0ull, a1p1=0ull;
    #pragma unroll
    for (int kk = 0; kk < Lv; kk++) {
        float a0 = s_left[l00*Lv + kk];
        float a1 = s_left[(l00+1)*Lv + kk];
        ulonglong2 b = *(const ulonglong2*)&s_y[kk*kD + v0];
        ull ad0 = pdup(a0), ad1 = pdup(a1);
        fma2(a0p0, ad0, b.x); fma2(a0p1, ad0, b.y);
        fma2(a1p0, ad1, b.x); fma2(a1p1, ad1, b.y);
    }
    float2 r00 = up2(a0p0), r01 = up2(a0p1), r10 = up2(a1p0), r11 = up2(a1p1);
    *(float4*)&out[((size_t)bh*kS + (size_t)l00*BSv + j)*kD + v0] =
        make_float4(r00.x,r00.y,r01.x,r01.y);
    *(float4*)&out[((size_t)bh*kS + (size_t)(l00+1)*BSv + j)*kD + v0] =
        make_float4(r10.x,r10.y,r11.x,r11.y);
}

// ---------------- launch ----------------
extern "C" void kernel_launch(void* const* d_in, const int* in_sizes, int n_in,
                              void* d_out, int out_size) {
    (void)in_sizes; (void)n_in; (void)out_size;
    const float* q      = (const float*)d_in[0];
    const float* key    = (const float*)d_in[1];
    const float* val    = (const float*)d_in[2];
    const float* ascale = (const float*)d_in[3];
    const float* ssz    = (const float*)d_in[4];
    float* out = (float*)d_out;

    const size_t SMEM_R = (size_t)SMEM_RT_FLOATS * sizeof(float);
    cudaFuncSetAttribute(right_step_kernel<true,0>,  cudaFuncAttributeMaxDynamicSharedMemorySize, (int)SMEM_R);
    cudaFuncSetAttribute(right_step_kernel<false,0>, cudaFuncAttributeMaxDynamicSharedMemorySize, (int)SMEM_R);
    cudaFuncSetAttribute(right_step_kernel<false,1>, cudaFuncAttributeMaxDynamicSharedMemorySize, (int)SMEM_R);

    prep_kernel<<<1, 128>>>(ascale, ssz);
    init_kr_kernel<<<BH*Lv, 256>>>(key);

    // s = 0 (INIT: lp/rp are exact constants, skip the global reads)
    left_step_kernel<true,false><<<BH*BSv, 256>>>(q, 0);
    right_step_kernel<true,0><<<BH*Lv, 256, SMEM_R>>>(key, val, 0);
    // s = 1..2
    for (int s = 1; s < NSTEPS-1; s++) {
        left_step_kernel<false,false><<<BH*BSv, 256>>>(q, s);
        right_step_kernel<false,0><<<BH*Lv, 256, SMEM_R>>>(key, val, s);
    }
    // s = 3 (LAST: left -> leftF, right -> Y from V)
    left_step_kernel<false,true><<<BH*BSv, 256>>>(q, NSTEPS-1);
    right_step_kernel<false,1><<<BH*Lv, 256, SMEM_R>>>(key, val, NSTEPS-1);

    zout_kernel<<<BH*BSv, 256>>>(out);
}